// round 16
// baseline (speedup 1.0000x reference)
#include <cuda_runtime.h>
#include <cuda_bf16.h>

#define BB     4
#define NN     8192
#define CC     256
#define POOLN  2048
#define NBR    4
#define TILE_PTS   1024                  // smem tile: first 1024 points of the batch
#define QPB    16                        // queries (warps) per block
#define NTHREADS 512
#define SEGF   (NN / QPB)                // 512 points per warp segment (hard phase)

__device__ __forceinline__ float decode_radius(const int* radius_raw)
{
    const unsigned rv = (unsigned)__ldg(radius_raw);
    return (rv & 0x7F800000u) ? __int_as_float((int)rv) : (float)(int)rv;
}

// Single fused kernel: 16 queries per 512-thread block.
// Easy phase: warp-per-query scan of a packed smem tile (first 1024 points).
// Hard phase: for the rare unresolved queries of THIS block, all 16 warps
// cooperatively full-scan N=8192 (coalesced 512-pt segments, staged loads),
// merge in segment order, gather. One graph node, zero global state.
__global__ __launch_bounds__(NTHREADS, 3)
void pool_fused_kernel(const float* __restrict__ verts,
                       const float* __restrict__ feat,
                       const int*   __restrict__ radius_raw,
                       const int*   __restrict__ sample_idx,
                       float* __restrict__ outV,
                       float* __restrict__ outF)
{
    __shared__ float4   s_tile[TILE_PTS];   // (x, y, z, |p|^2), 16 KB
    __shared__ unsigned s_hard;
    __shared__ int      s_cnt[QPB];
    __shared__ int      s_list[QPB][NBR];
    __shared__ int      s_idx[NBR];

    const int wid  = threadIdx.x >> 5;
    const int lane = threadIdx.x & 31;
    const int qid  = blockIdx.x * QPB + wid;   // block never straddles batches
    const int b    = qid >> 11;                // / POOLN
    const int s    = qid & (POOLN - 1);

    if (threadIdx.x == 0) s_hard = 0;

    const float* vb = verts + (size_t)b * NN * 3;

    // Cooperative packed tile load: 2 points per thread.
    #pragma unroll
    for (int i = 0; i < TILE_PTS / NTHREADS; i++) {
        const int p = threadIdx.x + i * NTHREADS;
        const float px = vb[3 * p + 0];
        const float py = vb[3 * p + 1];
        const float pz = vb[3 * p + 2];
        s_tile[p] = make_float4(px, py, pz, px * px + py * py + pz * pz);
    }

    const int n = sample_idx[s];
    const float qx = vb[n * 3 + 0];
    const float qy = vb[n * 3 + 1];
    const float qz = vb[n * 3 + 2];
    const float sqn = qx * qx + qy * qy + qz * qz;

    const float radius = decode_radius(radius_raw);
    const float r2 = radius * radius;

    // vertices_pool (always)
    if (lane < 3) {
        const float v = (lane == 0) ? qx : (lane == 1) ? qy : qz;
        outV[((size_t)b * POOLN + s) * 3 + lane] = v;
    }

    __syncthreads();

    // ---- easy scan over packed smem tile: first NBR ascending qualifiers ----
    int idx[NBR];
    int cnt = 0;
    #pragma unroll
    for (int k = 0; k < NBR; k++) idx[k] = n;

    for (int base = 0; base < TILE_PTS; base += 128) {
        unsigned bal[4];
        #pragma unroll
        for (int t = 0; t < 4; t++) {
            const float4 P = s_tile[base + t * 32 + lane];
            // same evaluation order as reference: (-2*dot + sq_n) + sq_m
            const float d = -2.0f * (P.x * qx + P.y * qy + P.z * qz) + sqn + P.w;
            bal[t] = __ballot_sync(0xFFFFFFFFu, !(d > r2));
        }
        #pragma unroll
        for (int t = 0; t < 4; t++) {
            unsigned m = bal[t];
            while (m && cnt < NBR) {
                idx[cnt++] = base + t * 32 + (__ffs(m) - 1);
                m &= m - 1;
            }
        }
        if (cnt >= NBR) break;   // uniform (ballot-derived)
    }

    if (cnt < NBR) {
        if (lane == 0) atomicOr(&s_hard, 1u << wid);
    } else {
        // ---- gather 4 feature rows (two batches of 4 float4), max, store ----
        const float* fb = feat + (size_t)b * NN * CC;
        const float4* __restrict__ f0 = (const float4*)(fb + (size_t)idx[0] * CC);
        const float4* __restrict__ f1 = (const float4*)(fb + (size_t)idx[1] * CC);
        const float4* __restrict__ f2 = (const float4*)(fb + (size_t)idx[2] * CC);
        const float4* __restrict__ f3 = (const float4*)(fb + (size_t)idx[3] * CC);
        float4* __restrict__ fo = (float4*)(outF + ((size_t)b * POOLN + s) * CC);

        #pragma unroll
        for (int h = 0; h < 2; h++) {
            const int c = lane + h * 32;
            const float4 a0 = f0[c], a1 = f1[c], a2 = f2[c], a3 = f3[c];
            float4 r;
            r.x = fmaxf(fmaxf(a0.x, a1.x), fmaxf(a2.x, a3.x));
            r.y = fmaxf(fmaxf(a0.y, a1.y), fmaxf(a2.y, a3.y));
            r.z = fmaxf(fmaxf(a0.z, a1.z), fmaxf(a2.z, a3.z));
            r.w = fmaxf(fmaxf(a0.w, a1.w), fmaxf(a2.w, a3.w));
            fo[c] = r;
        }
    }

    __syncthreads();
    unsigned hm = s_hard;                      // uniform across the block

    // ---- hard phase: all 16 warps cooperate per flagged query ----
    while (hm) {
        const int hw = __ffs(hm) - 1;
        hm &= hm - 1;

        const int hs = (blockIdx.x * QPB + hw) & (POOLN - 1);
        const int hn = sample_idx[hs];
        const float hqx = vb[hn * 3 + 0];
        const float hqy = vb[hn * 3 + 1];
        const float hqz = vb[hn * 3 + 2];
        const float hsq = hqx * hqx + hqy * hqy + hqz * hqz;

        const int seg = wid * SEGF;            // this warp's 512-point segment

        // per-lane 16-bit qualifier mask; loads staged 8 points deep
        unsigned lm = 0;
        #pragma unroll
        for (int half = 0; half < 2; half++) {
            float vx[8], vy[8], vz[8];
            #pragma unroll
            for (int j = 0; j < 8; j++) {
                const int p = seg + (half * 8 + j) * 32 + lane;
                vx[j] = vb[3 * p + 0];
                vy[j] = vb[3 * p + 1];
                vz[j] = vb[3 * p + 2];
            }
            #pragma unroll
            for (int j = 0; j < 8; j++) {
                const float d = -2.0f * (vx[j] * hqx + vy[j] * hqy + vz[j] * hqz) + hsq
                                + (vx[j] * vx[j] + vy[j] * vy[j] + vz[j] * vz[j]);
                lm |= ((unsigned)(!(d > r2))) << (half * 8 + j);
            }
        }

        // extract first NBR ascending qualifiers (index order = (j, lane))
        int hidx[NBR];
        #pragma unroll
        for (int k = 0; k < NBR; k++) hidx[k] = 0;
        int hcnt = 0;
        if (__ballot_sync(0xFFFFFFFFu, lm != 0)) {   // usually false
            for (int j = 0; j < 16 && hcnt < NBR; j++) {
                unsigned m = __ballot_sync(0xFFFFFFFFu, (lm >> j) & 1u);
                while (m && hcnt < NBR) {
                    hidx[hcnt++] = seg + j * 32 + (__ffs(m) - 1);
                    m &= m - 1;
                }
            }
        }

        if (lane == 0) {
            s_cnt[wid] = hcnt;
            #pragma unroll
            for (int k = 0; k < NBR; k++) s_list[wid][k] = hidx[k];
        }
        __syncthreads();

        // merge: segments ascending, lists internally ascending
        if (threadIdx.x == 0) {
            int tot = 0;
            #pragma unroll
            for (int ww = 0; ww < QPB; ww++) {
                const int cw = s_cnt[ww];
                for (int k = 0; k < cw && tot < NBR; k++)
                    s_idx[tot++] = s_list[ww][k];
                if (tot >= NBR) break;
            }
            // tot >= 1 always (self point qualifies in its own segment)
            for (int k = tot; k < NBR; k++) s_idx[k] = s_idx[0];
        }
        __syncthreads();

        // gather + max with 64 threads
        if (threadIdx.x < CC / 4) {
            const int t = threadIdx.x;
            const float* fb = feat + (size_t)b * NN * CC;
            const float4 a0 = ((const float4*)(fb + (size_t)s_idx[0] * CC))[t];
            const float4 a1 = ((const float4*)(fb + (size_t)s_idx[1] * CC))[t];
            const float4 a2 = ((const float4*)(fb + (size_t)s_idx[2] * CC))[t];
            const float4 a3 = ((const float4*)(fb + (size_t)s_idx[3] * CC))[t];
            float4 r;
            r.x = fmaxf(fmaxf(a0.x, a1.x), fmaxf(a2.x, a3.x));
            r.y = fmaxf(fmaxf(a0.y, a1.y), fmaxf(a2.y, a3.y));
            r.z = fmaxf(fmaxf(a0.z, a1.z), fmaxf(a2.z, a3.z));
            r.w = fmaxf(fmaxf(a0.w, a1.w), fmaxf(a2.w, a3.w));
            ((float4*)(outF + ((size_t)b * POOLN + hs) * CC))[t] = r;
        }
        __syncthreads();   // protect s_* reuse for next hard query
    }
}

extern "C" void kernel_launch(void* const* d_in, const int* in_sizes, int n_in,
                              void* d_out, int out_size)
{
    const float* verts      = (const float*)d_in[0];
    const float* feat       = (const float*)d_in[1];
    const int*   radius_raw = (const int*)  d_in[2];
    const int*   sample_idx = (const int*)  d_in[3];

    float* outV = (float*)d_out;
    float* outF = (float*)d_out + (size_t)BB * POOLN * 3;

    pool_fused_kernel<<<BB * POOLN / QPB, NTHREADS>>>(verts, feat, radius_raw,
                                                      sample_idx, outV, outF);
}